// round 6
// baseline (speedup 1.0000x reference)
#include <cuda_runtime.h>
#include <cstdint>

// Problem constants (fixed by setup_inputs)
#define BD   4
#define NH   4
#define HD   8
#define HH   256
#define WW   256
#define KS   5
#define AMP  2

// Tiling: 16x16 tile, 128 threads, 2 pixels per thread along x
#define TILE_Y 16
#define TILE_X 16
#define TXN    8
#define P      2
#define NTHR   128
#define SROWS  (TILE_Y + 2*AMP)   // 20
#define SCOLS  (TILE_X + 2*AMP)   // 20
#define CHELEMS (SROWS * SCOLS)   // 400
#define HEAD_ELEMS (HD * CHELEMS) // 3200

__device__ __forceinline__ uint32_t smem_u32(const void* p) {
    uint32_t a;
    asm("{ .reg .u64 t; cvta.to.shared.u64 t, %1; cvt.u32.u64 %0, t; }"
        : "=r"(a) : "l"(p));
    return a;
}
__device__ __forceinline__ float ex2f(float x) {
    float r; asm("ex2.approx.f32 %0, %1;" : "=f"(r) : "f"(x)); return r;
}
__device__ __forceinline__ float rcpf(float x) {
    float r; asm("rcp.approx.f32 %0, %1;" : "=f"(r) : "f"(x)); return r;
}
__device__ __forceinline__ void cp4(uint32_t s, const float* g, bool v) {
    int sz = v ? 4 : 0;
    asm volatile("cp.async.ca.shared.global [%0], [%1], 4, %2;"
                 :: "r"(s), "l"(g), "r"(sz));
}

__device__ __forceinline__ void stage_head(uint32_t sbase,
                                           const float* __restrict__ xk_b,
                                           int h, int x0, int y0, int tid)
{
    // 3200 elems / 128 threads = 25 iterations exactly
    #pragma unroll
    for (int it = 0; it < HEAD_ELEMS / NTHR; ++it) {
        int idx = it * NTHR + tid;
        int c   = idx / CHELEMS;
        int rem = idx - c * CHELEMS;
        int r   = rem / SCOLS;
        int m   = rem - r * SCOLS;
        int gy  = y0 - AMP + r;
        int gx  = x0 - AMP + m;
        bool v  = (gy >= 0) & (gy < HH) & (gx >= 0) & (gx < WW);
        int gyc = v ? gy : 0;
        int gxc = v ? gx : 0;
        const float* g = xk_b + ((c * NH + h) << 16) + (gyc << 8) + gxc;
        cp4(sbase + (uint32_t)idx * 4u, g, v);
    }
    asm volatile("cp.async.commit_group;" ::: "memory");
}

__global__ __launch_bounds__(NTHR, 8)
void cover_kernel(const float* __restrict__ xq,
                  const float* __restrict__ xk,
                  float* __restrict__ out)
{
    // double-buffered per-head k tile: 2 x 8ch x 20 x 20 floats = 25600 B
    __shared__ __align__(16) float sk[2][HD][SROWS][SCOLS];

    const int tid = threadIdx.x;
    const int tx  = tid & (TXN - 1);   // 0..7
    const int ty  = tid >> 3;          // 0..15
    const int x0  = blockIdx.x * TILE_X;
    const int y0  = blockIdx.y * TILE_Y;
    const int b   = blockIdx.z;
    const int y   = y0 + ty;
    const int xg  = x0 + tx * P;

    const uint32_t sb0 = smem_u32(&sk[0][0][0][0]);
    const uint32_t sb1 = smem_u32(&sk[1][0][0][0]);

    // validity bitmasks (di/dj in 0..4 -> spatial offset -2..+2)
    unsigned rowbits = 0;
    #pragma unroll
    for (int di = 0; di < KS; ++di) {
        int yy = y + di - AMP;
        if (yy >= 0 && yy < HH) rowbits |= (1u << di);
    }
    unsigned colbits[P];
    #pragma unroll
    for (int p = 0; p < P; ++p) {
        unsigned cb = 0;
        #pragma unroll
        for (int dj = 0; dj < KS; ++dj) {
            int xx = xg + p + dj - AMP;
            if (xx >= 0 && xx < WW) cb |= (1u << dj);
        }
        colbits[p] = cb;
    }
    const bool allvalid = (rowbits == 0x1Fu) &&
        ((colbits[0] & colbits[1]) == 0x1Fu);

    // fold log2(e) into q scale: exp(score) = exp2(score*log2e)
    const float qscale = 0.35355339059327373f * 1.4426950408889634f;
    const long plane = (long)HH * WW;

    const float* xq_b = xq + (long)b * (NH * HD) * plane;
    const float* xk_b = xk + (long)b * (NH * HD) * plane;

    float outy[P] = {0.f, 0.f};
    float outx[P] = {0.f, 0.f};

    // prologue: stage heads 0 and 1
    stage_head(sb0, xk_b, 0, x0, y0, tid);
    stage_head(sb1, xk_b, 1, x0, y0, tid);

    #pragma unroll 1
    for (int h = 0; h < NH; ++h) {
        if (h == NH - 1) asm volatile("cp.async.wait_group 0;" ::: "memory");
        else             asm volatile("cp.async.wait_group 1;" ::: "memory");
        __syncthreads();

        // per-head base pointer; (c,di) offsets are compile-time constants
        const float* kb = (h & 1) ? &sk[1][0][ty][tx * P]
                                  : &sk[0][0][ty][tx * P];

        // q for this head: 8 channels x 2 pixels
        float q[HD][P];
        #pragma unroll
        for (int c = 0; c < HD; ++c) {
            float2 qv = *reinterpret_cast<const float2*>(
                xq_b + ((c * NH + h) << 16) + (y << 8) + xg);
            q[c][0] = qv.x * qscale;
            q[c][1] = qv.y * qscale;
        }

        float s[P]  = {0.f, 0.f};
        float oy[P] = {0.f, 0.f};
        float ox[P] = {0.f, 0.f};

        #pragma unroll
        for (int di = 0; di < KS; ++di) {
            float a[KS][P];
            #pragma unroll
            for (int dj = 0; dj < KS; ++dj)
                #pragma unroll
                for (int p = 0; p < P; ++p) a[dj][p] = 0.f;

            #pragma unroll
            for (int c = 0; c < HD; ++c) {
                // constant offset: c*400 + di*20 (folds into LDS immediates)
                const float* krow = kb + c * CHELEMS + di * SCOLS;
                float2 k01 = *reinterpret_cast<const float2*>(krow);
                float2 k23 = *reinterpret_cast<const float2*>(krow + 2);
                float2 k45 = *reinterpret_cast<const float2*>(krow + 4);
                float kk[6] = {k01.x, k01.y, k23.x, k23.y, k45.x, k45.y};
                #pragma unroll
                for (int dj = 0; dj < KS; ++dj)
                    #pragma unroll
                    for (int p = 0; p < P; ++p)
                        a[dj][p] = fmaf(q[c][p], kk[p + dj], a[dj][p]);
            }

            const float fdi = (float)(di - AMP);
            if (allvalid) {
                #pragma unroll
                for (int p = 0; p < P; ++p) {
                    float w0 = ex2f(a[0][p]);
                    float w1 = ex2f(a[1][p]);
                    float w2 = ex2f(a[2][p]);
                    float w3 = ex2f(a[3][p]);
                    float w4 = ex2f(a[4][p]);
                    float rs = ((w0 + w1) + (w2 + w3)) + w4;
                    float cs = fmaf(2.f, w4 - w0, w3 - w1);
                    s[p]  += rs;
                    oy[p]  = fmaf(rs, fdi, oy[p]);
                    ox[p] += cs;
                }
            } else {
                const bool rvalid = (rowbits >> di) & 1u;
                #pragma unroll
                for (int p = 0; p < P; ++p) {
                    const unsigned cb = colbits[p];
                    float w[KS];
                    #pragma unroll
                    for (int dj = 0; dj < KS; ++dj) {
                        bool valid = rvalid && ((cb >> dj) & 1u);
                        w[dj] = valid ? ex2f(a[dj][p]) : 0.f;
                    }
                    float rs = ((w[0] + w[1]) + (w[2] + w[3])) + w[4];
                    float cs = fmaf(2.f, w[4] - w[0], w[3] - w[1]);
                    s[p]  += rs;
                    oy[p]  = fmaf(rs, fdi, oy[p]);
                    ox[p] += cs;
                }
            }
        }

        #pragma unroll
        for (int p = 0; p < P; ++p) {
            float inv = rcpf(s[p]);
            outy[p] = fmaf(oy[p], inv, outy[p]);
            outx[p] = fmaf(ox[p], inv, outx[p]);
        }

        __syncthreads();  // all readers done with buf before restaging it
        if (h + 2 < NH)
            stage_head((h & 1) ? sb1 : sb0, xk_b, h + 2, x0, y0, tid);
    }

    // mean over heads, write (B, 2, H, W): ch0 = row offset, ch1 = col offset
    const float invh = 1.0f / (float)NH;
    float* ob = out + (long)b * 2 * plane;
    float2 o0 = make_float2(outy[0] * invh, outy[1] * invh);
    float2 o1 = make_float2(outx[0] * invh, outx[1] * invh);
    *reinterpret_cast<float2*>(ob + (y << 8) + xg) = o0;
    *reinterpret_cast<float2*>(ob + plane + (y << 8) + xg) = o1;
}

extern "C" void kernel_launch(void* const* d_in, const int* in_sizes, int n_in,
                              void* d_out, int out_size)
{
    const float* xq = (const float*)d_in[0];
    const float* xk = (const float*)d_in[1];
    float* out = (float*)d_out;
    (void)in_sizes; (void)n_in; (void)out_size;

    dim3 grid(WW / TILE_X, HH / TILE_Y, BD);  // (16, 16, 4) = 1024 blocks
    cover_kernel<<<grid, NTHR>>>(xq, xk, out);
}

// round 8
// speedup vs baseline: 1.3965x; 1.3965x over previous
#include <cuda_runtime.h>
#include <cstdint>

// Problem constants (fixed by setup_inputs)
#define BD   4
#define NH   4
#define HD   8
#define HH   256
#define WW   256
#define KS   5
#define AMP  2

// Tiling: 32x16 tile, 256 threads, 2 pixels per thread along x
#define TILE_Y 16
#define TILE_X 32
#define TXN    16
#define P      2
#define NTHR   256
#define SROWS  (TILE_Y + 2*AMP)   // 20
#define SCOLS  36                 // logical halo columns
#define SCOLS_S 40                // padded storage row (160B, 16B-aligned)
#define CHELEMS_S (SROWS * SCOLS_S)  // 800
#define NROWS  (HD * SROWS)       // 160 rows per head tile

__device__ __forceinline__ uint32_t smem_u32(const void* p) {
    uint32_t a;
    asm("{ .reg .u64 t; cvta.to.shared.u64 t, %1; cvt.u32.u64 %0, t; }"
        : "=r"(a) : "l"(p));
    return a;
}
__device__ __forceinline__ float ex2f(float x) {
    float r; asm("ex2.approx.f32 %0, %1;" : "=f"(r) : "f"(x)); return r;
}
__device__ __forceinline__ float rcpf(float x) {
    float r; asm("rcp.approx.f32 %0, %1;" : "=f"(r) : "f"(x)); return r;
}
__device__ __forceinline__ void cp4(uint32_t s, const float* g) {
    asm volatile("cp.async.ca.shared.global [%0], [%1], 4;"
                 :: "r"(s), "l"(g));
}
__device__ __forceinline__ void cp16(uint32_t s, const float* g) {
    asm volatile("cp.async.ca.shared.global [%0], [%1], 16;"
                 :: "r"(s), "l"(g));
}
__device__ __forceinline__ int clampi(int v, int lo, int hi) {
    return min(max(v, lo), hi);
}

// Clamp-address staging: out-of-image slots get nearby real (finite) k values
// that are never consumed — their softmax weights are zeroed by the bitmasks.
// Logical halo column m is stored at s-col m+2 so that gmem (x0-2+m) and smem
// offsets are BOTH 16B-aligned exactly when m % 4 == 2.
__device__ __forceinline__ void stage_head(uint32_t sbase,
                                           const float* __restrict__ xk_b,
                                           int h, int x0, int y0, int tid)
{
    // interior: m = 2,6,...,30 -> 8 cp16 per row, covers floats 2..33
    // (in-image in x for every tile); 160 rows * 8 = 1280 ops, 5 iters
    #pragma unroll
    for (int it = 0; it < 5; ++it) {
        int idx  = it * NTHR + tid;
        int rall = idx >> 3;              // 0..159
        int e    = idx & 7;               // 0..7
        int m    = 2 + e * 4;             // 2,6,...,30
        int c    = rall / SROWS;
        int r    = rall - c * SROWS;
        int gy   = clampi(y0 - AMP + r, 0, HH - 1);
        int gx   = x0 - AMP + m;          // >= x0, <= x0+31 : always in-image
        const float* g = xk_b + ((c * NH + h) << 16) + (gy << 8) + gx;
        cp16(sbase + (uint32_t)(c * CHELEMS_S + r * SCOLS_S + m + 2) * 4u, g);
    }
    // edges: m in {0,1,34,35} -> 4 scalars per row; 640 ops, 2.5 iters
    #pragma unroll
    for (int it = 0; it < 3; ++it) {
        int idx  = it * NTHR + tid;
        if (it == 2 && idx >= NROWS * 4) break;
        int rall = idx >> 2;              // 0..159
        int e    = idx & 3;               // 0..3
        int m    = (e < 2) ? e : e + 32;  // {0,1,34,35}
        int c    = rall / SROWS;
        int r    = rall - c * SROWS;
        int gy   = clampi(y0 - AMP + r, 0, HH - 1);
        int gx   = clampi(x0 - AMP + m, 0, WW - 1);
        const float* g = xk_b + ((c * NH + h) << 16) + (gy << 8) + gx;
        cp4(sbase + (uint32_t)(c * CHELEMS_S + r * SCOLS_S + m + 2) * 4u, g);
    }
    asm volatile("cp.async.commit_group;" ::: "memory");
}

__global__ __launch_bounds__(NTHR, 4)
void cover_kernel(const float* __restrict__ xq,
                  const float* __restrict__ xk,
                  float* __restrict__ out)
{
    // double-buffered per-head k tile: 2 x 8ch x 20 x 40 floats = 51200 B
    __shared__ __align__(16) float sk[2][HD][SROWS][SCOLS_S];

    const int tid = threadIdx.x;
    const int tx  = tid & (TXN - 1);   // 0..15
    const int ty  = tid >> 4;          // 0..15
    const int x0  = blockIdx.x * TILE_X;
    const int y0  = blockIdx.y * TILE_Y;
    const int b   = blockIdx.z;
    const int y   = y0 + ty;
    const int xg  = x0 + tx * P;

    const uint32_t sb0 = smem_u32(&sk[0][0][0][0]);
    const uint32_t sb1 = smem_u32(&sk[1][0][0][0]);

    // validity bitmasks (di/dj in 0..4 -> spatial offset -2..+2)
    unsigned rowbits = 0;
    #pragma unroll
    for (int di = 0; di < KS; ++di) {
        int yy = y + di - AMP;
        if (yy >= 0 && yy < HH) rowbits |= (1u << di);
    }
    unsigned colbits[P];
    #pragma unroll
    for (int p = 0; p < P; ++p) {
        unsigned cb = 0;
        #pragma unroll
        for (int dj = 0; dj < KS; ++dj) {
            int xx = xg + p + dj - AMP;
            if (xx >= 0 && xx < WW) cb |= (1u << dj);
        }
        colbits[p] = cb;
    }
    const bool allvalid = (rowbits == 0x1Fu) &&
        ((colbits[0] & colbits[1]) == 0x1Fu);

    // fold log2(e) into q scale: exp(score) = exp2(score*log2e)
    const float qscale = 0.35355339059327373f * 1.4426950408889634f;
    const long plane = (long)HH * WW;

    const float* xq_b = xq + (long)b * (NH * HD) * plane;
    const float* xk_b = xk + (long)b * (NH * HD) * plane;

    float outy[P] = {0.f, 0.f};
    float outx[P] = {0.f, 0.f};

    // prologue: stage heads 0 and 1
    stage_head(sb0, xk_b, 0, x0, y0, tid);
    stage_head(sb1, xk_b, 1, x0, y0, tid);

    #pragma unroll 1
    for (int h = 0; h < NH; ++h) {
        // preload q (gmem, independent of smem) BEFORE the barrier: LDG
        // latency overlaps the cp.async wait + syncthreads
        float2 qv[HD];
        #pragma unroll
        for (int c = 0; c < HD; ++c)
            qv[c] = *reinterpret_cast<const float2*>(
                xq_b + ((c * NH + h) << 16) + (y << 8) + xg);

        if (h == NH - 1) asm volatile("cp.async.wait_group 0;" ::: "memory");
        else             asm volatile("cp.async.wait_group 1;" ::: "memory");
        __syncthreads();

        // per-head smem base (+2 storage shift); (c,di) offsets = immediates
        const float* kb = (h & 1) ? &sk[1][0][ty][tx * P + 2]
                                  : &sk[0][0][ty][tx * P + 2];

        float q[HD][P];
        #pragma unroll
        for (int c = 0; c < HD; ++c) {
            q[c][0] = qv[c].x * qscale;
            q[c][1] = qv[c].y * qscale;
        }

        float s[P]  = {0.f, 0.f};
        float oy[P] = {0.f, 0.f};
        float ox[P] = {0.f, 0.f};

        #pragma unroll
        for (int di = 0; di < KS; ++di) {
            float a[KS][P];
            #pragma unroll
            for (int dj = 0; dj < KS; ++dj)
                #pragma unroll
                for (int p = 0; p < P; ++p) a[dj][p] = 0.f;

            #pragma unroll
            for (int c = 0; c < HD; ++c) {
                const float* krow = kb + c * CHELEMS_S + di * SCOLS_S;
                float2 k01 = *reinterpret_cast<const float2*>(krow);
                float2 k23 = *reinterpret_cast<const float2*>(krow + 2);
                float2 k45 = *reinterpret_cast<const float2*>(krow + 4);
                float kk[6] = {k01.x, k01.y, k23.x, k23.y, k45.x, k45.y};
                #pragma unroll
                for (int dj = 0; dj < KS; ++dj)
                    #pragma unroll
                    for (int p = 0; p < P; ++p)
                        a[dj][p] = fmaf(q[c][p], kk[p + dj], a[dj][p]);
            }

            const float fdi = (float)(di - AMP);
            if (allvalid) {
                #pragma unroll
                for (int p = 0; p < P; ++p) {
                    float w0 = ex2f(a[0][p]);
                    float w1 = ex2f(a[1][p]);
                    float w2 = ex2f(a[2][p]);
                    float w3 = ex2f(a[3][p]);
                    float w4 = ex2f(a[4][p]);
                    float rs = ((w0 + w1) + (w2 + w3)) + w4;
                    float cs = fmaf(2.f, w4 - w0, w3 - w1);
                    s[p]  += rs;
                    oy[p]  = fmaf(rs, fdi, oy[p]);
                    ox[p] += cs;
                }
            } else {
                const bool rvalid = (rowbits >> di) & 1u;
                #pragma unroll
                for (int p = 0; p < P; ++p) {
                    const unsigned cb = colbits[p];
                    float w[KS];
                    #pragma unroll
                    for (int dj = 0; dj < KS; ++dj) {
                        bool valid = rvalid && ((cb >> dj) & 1u);
                        w[dj] = valid ? ex2f(a[dj][p]) : 0.f;
                    }
                    float rs = ((w[0] + w[1]) + (w[2] + w[3])) + w[4];
                    float cs = fmaf(2.f, w[4] - w[0], w[3] - w[1]);
                    s[p]  += rs;
                    oy[p]  = fmaf(rs, fdi, oy[p]);
                    ox[p] += cs;
                }
            }
        }

        #pragma unroll
        for (int p = 0; p < P; ++p) {
            float inv = rcpf(s[p]);
            outy[p] = fmaf(oy[p], inv, outy[p]);
            outx[p] = fmaf(ox[p], inv, outx[p]);
        }

        __syncthreads();  // all readers done with buf before restaging it
        if (h + 2 < NH)
            stage_head((h & 1) ? sb1 : sb0, xk_b, h + 2, x0, y0, tid);
    }

    // mean over heads, write (B, 2, H, W): ch0 = row offset, ch1 = col offset
    const float invh = 1.0f / (float)NH;
    float* ob = out + (long)b * 2 * plane;
    float2 o0 = make_float2(outy[0] * invh, outy[1] * invh);
    float2 o1 = make_float2(outx[0] * invh, outx[1] * invh);
    *reinterpret_cast<float2*>(ob + (y << 8) + xg) = o0;
    *reinterpret_cast<float2*>(ob + plane + (y << 8) + xg) = o1;
}

extern "C" void kernel_launch(void* const* d_in, const int* in_sizes, int n_in,
                              void* d_out, int out_size)
{
    const float* xq = (const float*)d_in[0];
    const float* xk = (const float*)d_in[1];
    float* out = (float*)d_out;
    (void)in_sizes; (void)n_in; (void)out_size;

    dim3 grid(WW / TILE_X, HH / TILE_Y, BD);  // (8, 16, 4) = 512 blocks
    cover_kernel<<<grid, NTHR>>>(xq, xk, out);
}

// round 9
// speedup vs baseline: 1.5296x; 1.0954x over previous
#include <cuda_runtime.h>
#include <cstdint>

// Problem constants (fixed by setup_inputs)
#define BD   4
#define NH   4
#define HD   8
#define HH   256
#define WW   256
#define KS   5
#define AMP  2

// Tiling: 32x8 tile, 128 threads, 2 pixels per thread along x
#define TILE_Y 8
#define TILE_X 32
#define TXN    16
#define P      2
#define NTHR   128
#define SROWS  (TILE_Y + 2*AMP)   // 12
#define SCOLS_S 36                // 144B row: bank-clean, 8B-aligned cp8
#define CHELEMS_S (SROWS * SCOLS_S)  // 432
#define NROWS  (HD * SROWS)       // 96 rows per head tile

__device__ __forceinline__ uint32_t smem_u32(const void* p) {
    uint32_t a;
    asm("{ .reg .u64 t; cvta.to.shared.u64 t, %1; cvt.u32.u64 %0, t; }"
        : "=r"(a) : "l"(p));
    return a;
}
__device__ __forceinline__ float ex2f(float x) {
    float r; asm("ex2.approx.f32 %0, %1;" : "=f"(r) : "f"(x)); return r;
}
__device__ __forceinline__ float rcpf(float x) {
    float r; asm("rcp.approx.f32 %0, %1;" : "=f"(r) : "f"(x)); return r;
}
__device__ __forceinline__ void cp4(uint32_t s, const float* g) {
    asm volatile("cp.async.ca.shared.global [%0], [%1], 4;"
                 :: "r"(s), "l"(g));
}
__device__ __forceinline__ void cp8(uint32_t s, const float* g) {
    asm volatile("cp.async.ca.shared.global [%0], [%1], 8;"
                 :: "r"(s), "l"(g));
}
__device__ __forceinline__ int clampi(int v, int lo, int hi) {
    return min(max(v, lo), hi);
}

// Clamp-address staging: out-of-image slots hold nearby real (finite) k values
// that are never consumed (their softmax weights are zeroed by the bitmasks).
// Logical halo col m stored at s-col m. For even m, both the gmem address
// (x0-2+m) and the smem offset ((...+m)*4) are 8B-aligned -> cp8.
__device__ __forceinline__ void stage_head(uint32_t sbase,
                                           const float* __restrict__ xk_b,
                                           int h, int x0, int y0, int tid)
{
    // interior: m = 2,4,...,32 -> 16 cp8/row, covers m=2..33 (always in-image
    // in x); 96 rows * 16 = 1536 ops = 12 iterations
    #pragma unroll
    for (int it = 0; it < 12; ++it) {
        int idx = it * NTHR + tid;
        int row = idx >> 4;               // 0..95
        int e   = idx & 15;               // 0..15
        int m   = 2 + 2 * e;              // 2,4,...,32
        int c   = row / SROWS;
        int r   = row - c * SROWS;
        int gy  = clampi(y0 - AMP + r, 0, HH - 1);
        int gx  = x0 - AMP + m;           // in [x0, x0+30]: always in-image
        const float* g = xk_b + ((c * NH + h) << 16) + (gy << 8) + gx;
        cp8(sbase + (uint32_t)(c * CHELEMS_S + r * SCOLS_S + m) * 4u, g);
    }
    // edges: m in {0,1,34,35} -> 4 scalars/row; 384 ops = 3 iterations
    #pragma unroll
    for (int it = 0; it < 3; ++it) {
        int idx = it * NTHR + tid;
        int row = idx >> 2;               // 0..95
        int e   = idx & 3;                // 0..3
        int m   = (e < 2) ? e : e + 32;   // {0,1,34,35}
        int c   = row / SROWS;
        int r   = row - c * SROWS;
        int gy  = clampi(y0 - AMP + r, 0, HH - 1);
        int gx  = clampi(x0 - AMP + m, 0, WW - 1);
        const float* g = xk_b + ((c * NH + h) << 16) + (gy << 8) + gx;
        cp4(sbase + (uint32_t)(c * CHELEMS_S + r * SCOLS_S + m) * 4u, g);
    }
    asm volatile("cp.async.commit_group;" ::: "memory");
}

__global__ __launch_bounds__(NTHR, 8)
void cover_kernel(const float* __restrict__ xq,
                  const float* __restrict__ xk,
                  float* __restrict__ out)
{
    // double-buffered per-head k tile: 2 x 8ch x 12 x 36 floats = 27648 B
    __shared__ __align__(16) float sk[2][HD][SROWS][SCOLS_S];

    const int tid = threadIdx.x;
    const int tx  = tid & (TXN - 1);   // 0..15
    const int ty  = tid >> 4;          // 0..7
    const int x0  = blockIdx.x * TILE_X;
    const int y0  = blockIdx.y * TILE_Y;
    const int b   = blockIdx.z;
    const int y   = y0 + ty;
    const int xg  = x0 + tx * P;

    const uint32_t sb0 = smem_u32(&sk[0][0][0][0]);
    const uint32_t sb1 = smem_u32(&sk[1][0][0][0]);

    // validity bitmasks (di/dj in 0..4 -> spatial offset -2..+2)
    unsigned rowbits = 0;
    #pragma unroll
    for (int di = 0; di < KS; ++di) {
        int yy = y + di - AMP;
        if (yy >= 0 && yy < HH) rowbits |= (1u << di);
    }
    unsigned colbits[P];
    #pragma unroll
    for (int p = 0; p < P; ++p) {
        unsigned cb = 0;
        #pragma unroll
        for (int dj = 0; dj < KS; ++dj) {
            int xx = xg + p + dj - AMP;
            if (xx >= 0 && xx < WW) cb |= (1u << dj);
        }
        colbits[p] = cb;
    }
    const bool allvalid = (rowbits == 0x1Fu) &&
        ((colbits[0] & colbits[1]) == 0x1Fu);

    // fold log2(e) into q scale: exp(score) = exp2(score*log2e)
    const float qscale = 0.35355339059327373f * 1.4426950408889634f;
    const long plane = (long)HH * WW;

    const float* xq_b = xq + (long)b * (NH * HD) * plane;
    const float* xk_b = xk + (long)b * (NH * HD) * plane;

    float outy[P] = {0.f, 0.f};
    float outx[P] = {0.f, 0.f};

    // prologue: stage head 0 only (depth-1 pipeline)
    stage_head(sb0, xk_b, 0, x0, y0, tid);

    #pragma unroll 1
    for (int h = 0; h < NH; ++h) {
        // preload q (gmem, independent of smem): LDG latency overlaps the
        // cp.async wait + barrier
        float2 qv[HD];
        #pragma unroll
        for (int c = 0; c < HD; ++c)
            qv[c] = *reinterpret_cast<const float2*>(
                xq_b + ((c * NH + h) << 16) + (y << 8) + xg);

        asm volatile("cp.async.wait_group 0;" ::: "memory");
        __syncthreads();
        // Single barrier per head: at this point every thread has finished
        // compute(h-1), so restaging the buffer head h-1 used is safe, and
        // head h's data is visible block-wide.
        if (h + 1 < NH)
            stage_head(((h + 1) & 1) ? sb1 : sb0, xk_b, h + 1, x0, y0, tid);

        // per-head smem base; (c,di) offsets become LDS immediates
        const float* kb = (h & 1) ? &sk[1][0][ty][tx * P]
                                  : &sk[0][0][ty][tx * P];

        float q[HD][P];
        #pragma unroll
        for (int c = 0; c < HD; ++c) {
            q[c][0] = qv[c].x * qscale;
            q[c][1] = qv[c].y * qscale;
        }

        float s[P]  = {0.f, 0.f};
        float oy[P] = {0.f, 0.f};
        float ox[P] = {0.f, 0.f};

        #pragma unroll
        for (int di = 0; di < KS; ++di) {
            float a[KS][P];
            #pragma unroll
            for (int dj = 0; dj < KS; ++dj)
                #pragma unroll
                for (int p = 0; p < P; ++p) a[dj][p] = 0.f;

            #pragma unroll
            for (int c = 0; c < HD; ++c) {
                const float* krow = kb + c * CHELEMS_S + di * SCOLS_S;
                float2 k01 = *reinterpret_cast<const float2*>(krow);
                float2 k23 = *reinterpret_cast<const float2*>(krow + 2);
                float2 k45 = *reinterpret_cast<const float2*>(krow + 4);
                float kk[6] = {k01.x, k01.y, k23.x, k23.y, k45.x, k45.y};
                #pragma unroll
                for (int dj = 0; dj < KS; ++dj)
                    #pragma unroll
                    for (int p = 0; p < P; ++p)
                        a[dj][p] = fmaf(q[c][p], kk[p + dj], a[dj][p]);
            }

            const float fdi = (float)(di - AMP);
            if (allvalid) {
                #pragma unroll
                for (int p = 0; p < P; ++p) {
                    float w0 = ex2f(a[0][p]);
                    float w1 = ex2f(a[1][p]);
                    float w2 = ex2f(a[2][p]);
                    float w3 = ex2f(a[3][p]);
                    float w4 = ex2f(a[4][p]);
                    float rs = ((w0 + w1) + (w2 + w3)) + w4;
                    float cs = fmaf(2.f, w4 - w0, w3 - w1);
                    s[p]  += rs;
                    oy[p]  = fmaf(rs, fdi, oy[p]);
                    ox[p] += cs;
                }
            } else {
                const bool rvalid = (rowbits >> di) & 1u;
                #pragma unroll
                for (int p = 0; p < P; ++p) {
                    const unsigned cb = colbits[p];
                    float w[KS];
                    #pragma unroll
                    for (int dj = 0; dj < KS; ++dj) {
                        bool valid = rvalid && ((cb >> dj) & 1u);
                        w[dj] = valid ? ex2f(a[dj][p]) : 0.f;
                    }
                    float rs = ((w[0] + w[1]) + (w[2] + w[3])) + w[4];
                    float cs = fmaf(2.f, w[4] - w[0], w[3] - w[1]);
                    s[p]  += rs;
                    oy[p]  = fmaf(rs, fdi, oy[p]);
                    ox[p] += cs;
                }
            }
        }

        #pragma unroll
        for (int p = 0; p < P; ++p) {
            float inv = rcpf(s[p]);
            outy[p] = fmaf(oy[p], inv, outy[p]);
            outx[p] = fmaf(ox[p], inv, outx[p]);
        }
    }

    // mean over heads, write (B, 2, H, W): ch0 = row offset, ch1 = col offset
    const float invh = 1.0f / (float)NH;
    float* ob = out + (long)b * 2 * plane;
    float2 o0 = make_float2(outy[0] * invh, outy[1] * invh);
    float2 o1 = make_float2(outx[0] * invh, outx[1] * invh);
    *reinterpret_cast<float2*>(ob + (y << 8) + xg) = o0;
    *reinterpret_cast<float2*>(ob + plane + (y << 8) + xg) = o1;
}

extern "C" void kernel_launch(void* const* d_in, const int* in_sizes, int n_in,
                              void* d_out, int out_size)
{
    const float* xq = (const float*)d_in[0];
    const float* xk = (const float*)d_in[1];
    float* out = (float*)d_out;
    (void)in_sizes; (void)n_in; (void)out_size;

    dim3 grid(WW / TILE_X, HH / TILE_Y, BD);  // (8, 32, 4) = 1024 blocks
    cover_kernel<<<grid, NTHR>>>(xq, xk, out);
}

// round 10
// speedup vs baseline: 1.6344x; 1.0685x over previous
#include <cuda_runtime.h>
#include <cstdint>

// Problem constants (fixed by setup_inputs)
#define BD   4
#define NH   4
#define HD   8
#define HH   256
#define WW   256
#define KS   5
#define AMP  2

// Tiling: 32x8 tile, 128 threads, 2 pixels per thread along x
#define TILE_Y 8
#define TILE_X 32
#define TXN    16
#define P      2
#define NTHR   128
#define SROWS  (TILE_Y + 2*AMP)   // 12
#define SCOLS_S 36                // 144B row: bank-clean, 8B-aligned cp8
#define CHELEMS_S (SROWS * SCOLS_S)  // 432
#define NROWS  (HD * SROWS)       // 96 rows per head tile

__device__ __forceinline__ uint32_t smem_u32(const void* p) {
    uint32_t a;
    asm("{ .reg .u64 t; cvta.to.shared.u64 t, %1; cvt.u32.u64 %0, t; }"
        : "=r"(a) : "l"(p));
    return a;
}
__device__ __forceinline__ float ex2f(float x) {
    float r; asm("ex2.approx.f32 %0, %1;" : "=f"(r) : "f"(x)); return r;
}
__device__ __forceinline__ float rcpf(float x) {
    float r; asm("rcp.approx.f32 %0, %1;" : "=f"(r) : "f"(x)); return r;
}
__device__ __forceinline__ void cp8(uint32_t s, const float* g) {
    asm volatile("cp.async.ca.shared.global [%0], [%1], 8;"
                 :: "r"(s), "l"(g));
}
__device__ __forceinline__ int clampi(int v, int lo, int hi) {
    return min(max(v, lo), hi);
}

// Clamp-address staging: out-of-image slots hold nearby real (finite) k values
// that are never consumed (their softmax weights are zeroed by the bitmasks).
// In-image columns always receive their CORRECT values.
__device__ __forceinline__ void stage_head(uint32_t sbase,
                                           const float* __restrict__ xk_b,
                                           int h, int x0, int y0, int tid)
{
    // interior: m = 2,4,...,32 -> 16 cp8/row (always in-image in x);
    // 96 rows * 16 = 1536 ops = 12 iterations
    #pragma unroll
    for (int it = 0; it < 12; ++it) {
        int idx = it * NTHR + tid;
        int row = idx >> 4;               // 0..95
        int e   = idx & 15;               // 0..15
        int m   = 2 + 2 * e;              // 2,4,...,32
        int c   = row / SROWS;
        int r   = row - c * SROWS;
        int gy  = clampi(y0 - AMP + r, 0, HH - 1);
        int gx  = x0 - AMP + m;           // in [x0, x0+30]: always in-image
        const float* g = xk_b + ((c * NH + h) << 16) + (gy << 8) + gx;
        cp8(sbase + (uint32_t)(c * CHELEMS_S + r * SCOLS_S + m) * 4u, g);
    }
    // edges: cols {0,1} and {34,35} as one cp8 each, address clamped EVEN so
    // alignment holds; when the pair is consumable its gmem address is exact.
    // 96 rows * 2 = 192 ops -> 2 iterations (second half-guarded)
    #pragma unroll
    for (int it = 0; it < 2; ++it) {
        int idx = it * NTHR + tid;
        if (it == 1 && idx >= NROWS * 2) break;
        int row = idx >> 1;               // 0..95
        int e   = idx & 1;                // 0: left pair, 1: right pair
        int m   = e ? 34 : 0;
        int c   = row / SROWS;
        int r   = row - c * SROWS;
        int gy  = clampi(y0 - AMP + r, 0, HH - 1);
        int gx  = e ? min(x0 + 32, WW - 2) : max(x0 - 2, 0);  // even by constr.
        const float* g = xk_b + ((c * NH + h) << 16) + (gy << 8) + gx;
        cp8(sbase + (uint32_t)(c * CHELEMS_S + r * SCOLS_S + m) * 4u, g);
    }
    asm volatile("cp.async.commit_group;" ::: "memory");
}

__global__ __launch_bounds__(NTHR, 7)
void cover_kernel(const float* __restrict__ xq,
                  const float* __restrict__ xk,
                  float* __restrict__ out)
{
    // double-buffered per-head k tile: 2 x 8ch x 12 x 36 floats = 27648 B
    __shared__ __align__(16) float sk[2][HD][SROWS][SCOLS_S];

    const int tid = threadIdx.x;
    const int tx  = tid & (TXN - 1);   // 0..15
    const int ty  = tid >> 4;          // 0..7
    const int x0  = blockIdx.x * TILE_X;
    const int y0  = blockIdx.y * TILE_Y;
    const int b   = blockIdx.z;
    const int y   = y0 + ty;
    const int xg  = x0 + tx * P;

    const uint32_t sb0 = smem_u32(&sk[0][0][0][0]);
    const uint32_t sb1 = smem_u32(&sk[1][0][0][0]);

    // validity bitmasks (di/dj in 0..4 -> spatial offset -2..+2)
    unsigned rowbits = 0;
    #pragma unroll
    for (int di = 0; di < KS; ++di) {
        int yy = y + di - AMP;
        if (yy >= 0 && yy < HH) rowbits |= (1u << di);
    }
    unsigned colbits[P];
    #pragma unroll
    for (int p = 0; p < P; ++p) {
        unsigned cb = 0;
        #pragma unroll
        for (int dj = 0; dj < KS; ++dj) {
            int xx = xg + p + dj - AMP;
            if (xx >= 0 && xx < WW) cb |= (1u << dj);
        }
        colbits[p] = cb;
    }
    const bool allvalid = (rowbits == 0x1Fu) &&
        ((colbits[0] & colbits[1]) == 0x1Fu);

    // fold log2(e) into q scale: exp(score) = exp2(score*log2e)
    const float qscale = 0.35355339059327373f * 1.4426950408889634f;
    const long plane = (long)HH * WW;

    const float* xq_b = xq + (long)b * (NH * HD) * plane;
    const float* xk_b = xk + (long)b * (NH * HD) * plane;

    float outy[P] = {0.f, 0.f};
    float outx[P] = {0.f, 0.f};

    // prologue: stage head 0 (depth-1 pipeline)
    stage_head(sb0, xk_b, 0, x0, y0, tid);

    #pragma unroll 1
    for (int h = 0; h < NH; ++h) {
        // preload q (gmem, independent of smem): LDG latency overlaps the
        // cp.async wait + barrier
        float2 qv[HD];
        #pragma unroll
        for (int c = 0; c < HD; ++c)
            qv[c] = *reinterpret_cast<const float2*>(
                xq_b + ((c * NH + h) << 16) + (y << 8) + xg);

        asm volatile("cp.async.wait_group 0;" ::: "memory");
        __syncthreads();
        // Single barrier per head: every thread finished compute(h-1), so
        // restaging h-1's buffer is safe, and head h's tile is visible.
        if (h + 1 < NH)
            stage_head(((h + 1) & 1) ? sb1 : sb0, xk_b, h + 1, x0, y0, tid);

        // per-head smem base; (c,di) offsets become LDS immediates
        const float* kb = (h & 1) ? &sk[1][0][ty][tx * P]
                                  : &sk[0][0][ty][tx * P];

        float q[HD][P];
        #pragma unroll
        for (int c = 0; c < HD; ++c) {
            q[c][0] = qv[c].x * qscale;
            q[c][1] = qv[c].y * qscale;
        }

        float s[P]  = {0.f, 0.f};
        float oy[P] = {0.f, 0.f};
        float ox[P] = {0.f, 0.f};

        #pragma unroll
        for (int di = 0; di < KS; ++di) {
            float a[KS][P];
            #pragma unroll
            for (int dj = 0; dj < KS; ++dj)
                #pragma unroll
                for (int p = 0; p < P; ++p) a[dj][p] = 0.f;

            // software-pipelined channel loop: channel c+1's k loads issue
            // BEFORE channel c's FMA block consumes its values
            const float* kr0 = kb + di * SCOLS_S;
            float2 k01 = *reinterpret_cast<const float2*>(kr0);
            float2 k23 = *reinterpret_cast<const float2*>(kr0 + 2);
            float2 k45 = *reinterpret_cast<const float2*>(kr0 + 4);
            #pragma unroll
            for (int c = 0; c < HD; ++c) {
                float2 c01 = k01, c23 = k23, c45 = k45;
                if (c + 1 < HD) {
                    const float* kr = kb + (c + 1) * CHELEMS_S + di * SCOLS_S;
                    k01 = *reinterpret_cast<const float2*>(kr);
                    k23 = *reinterpret_cast<const float2*>(kr + 2);
                    k45 = *reinterpret_cast<const float2*>(kr + 4);
                }
                float kk[6] = {c01.x, c01.y, c23.x, c23.y, c45.x, c45.y};
                #pragma unroll
                for (int dj = 0; dj < KS; ++dj)
                    #pragma unroll
                    for (int p = 0; p < P; ++p)
                        a[dj][p] = fmaf(q[c][p], kk[p + dj], a[dj][p]);
            }

            const float fdi = (float)(di - AMP);
            if (allvalid) {
                #pragma unroll
                for (int p = 0; p < P; ++p) {
                    float w0 = ex2f(a[0][p]);
                    float w1 = ex2f(a[1][p]);
                    float w2 = ex2f(a[2][p]);
                    float w3 = ex2f(a[3][p]);
                    float w4 = ex2f(a[4][p]);
                    float rs = ((w0 + w1) + (w2 + w3)) + w4;
                    float cs = fmaf(2.f, w4 - w0, w3 - w1);
                    s[p]  += rs;
                    if (di != 2) oy[p] = fmaf(rs, fdi, oy[p]);
                    ox[p] += cs;
                }
            } else {
                const bool rvalid = (rowbits >> di) & 1u;
                #pragma unroll
                for (int p = 0; p < P; ++p) {
                    const unsigned cb = colbits[p];
                    float w[KS];
                    #pragma unroll
                    for (int dj = 0; dj < KS; ++dj) {
                        bool valid = rvalid && ((cb >> dj) & 1u);
                        w[dj] = valid ? ex2f(a[dj][p]) : 0.f;
                    }
                    float rs = ((w[0] + w[1]) + (w[2] + w[3])) + w[4];
                    float cs = fmaf(2.f, w[4] - w[0], w[3] - w[1]);
                    s[p]  += rs;
                    if (di != 2) oy[p] = fmaf(rs, fdi, oy[p]);
                    ox[p] += cs;
                }
            }
        }

        #pragma unroll
        for (int p = 0; p < P; ++p) {
            float inv = rcpf(s[p]);
            outy[p] = fmaf(oy[p], inv, outy[p]);
            outx[p] = fmaf(ox[p], inv, outx[p]);
        }
    }

    // mean over heads, write (B, 2, H, W): ch0 = row offset, ch1 = col offset
    const float invh = 1.0f / (float)NH;
    float* ob = out + (long)b * 2 * plane;
    float2 o0 = make_float2(outy[0] * invh, outy[1] * invh);
    float2 o1 = make_float2(outx[0] * invh, outx[1] * invh);
    *reinterpret_cast<float2*>(ob + (y << 8) + xg) = o0;
    *reinterpret_cast<float2*>(ob + plane + (y << 8) + xg) = o1;
}

extern "C" void kernel_launch(void* const* d_in, const int* in_sizes, int n_in,
                              void* d_out, int out_size)
{
    const float* xq = (const float*)d_in[0];
    const float* xk = (const float*)d_in[1];
    float* out = (float*)d_out;
    (void)in_sizes; (void)n_in; (void)out_size;

    dim3 grid(WW / TILE_X, HH / TILE_Y, BD);  // (8, 32, 4) = 1024 blocks
    cover_kernel<<<grid, NTHR>>>(xq, xk, out);
}